// round 3
// baseline (speedup 1.0000x reference)
#include <cuda_runtime.h>

#define RESF  0.16f
#define XMINF -51.2f
#define YMINF -51.2f
#define EPSF  1e-5f
#define NEGF  -1000000000.0f

// Folded weights (BN fused, 9-feature input collapsed to 4 features + pillar bias)
__device__ float g_wx[64], g_wy[64], g_wz[64], g_wr[64];
__device__ float g_wxc[64], g_wyc[64], g_wzm[64], g_b1[64];
__device__ float g_w2[64 * 64];   // W2 * a2, row-major [j][c]
__device__ float g_b2[64];

// ---------------------------------------------------------------------------
// Prep kernel: fold BN params into weights; collapse feature structure.
// feat = [x, y, z, r, x-xc, y-yc, z-zm, x-xc, y-yc]
//   => x:(W1[0]+W1[4]+W1[7]), y:(W1[1]+W1[5]+W1[8]), z:(W1[2]+W1[6]), r:W1[3]
//      bias(p) = b1' - xc*(W1[4]+W1[7])a1 - yc*(W1[5]+W1[8])a1 - zm*W1[6]a1
// ---------------------------------------------------------------------------
__global__ void pfn_prep(const float* __restrict__ W1, const float* __restrict__ b1,
                         const float* __restrict__ g1, const float* __restrict__ beta1,
                         const float* __restrict__ m1, const float* __restrict__ v1,
                         const float* __restrict__ W2, const float* __restrict__ b2,
                         const float* __restrict__ g2, const float* __restrict__ beta2,
                         const float* __restrict__ m2, const float* __restrict__ v2) {
    int j = threadIdx.x;
    if (j >= 64) return;
    float a1 = g1[j] * rsqrtf(v1[j] + EPSF);
    float w4 = W1[4 * 64 + j], w5 = W1[5 * 64 + j], w6 = W1[6 * 64 + j];
    float w7 = W1[7 * 64 + j], w8 = W1[8 * 64 + j];
    g_wx[j]  = (W1[0 * 64 + j] + w4 + w7) * a1;
    g_wy[j]  = (W1[1 * 64 + j] + w5 + w8) * a1;
    g_wz[j]  = (W1[2 * 64 + j] + w6) * a1;
    g_wr[j]  = W1[3 * 64 + j] * a1;
    g_wxc[j] = (w4 + w7) * a1;
    g_wyc[j] = (w5 + w8) * a1;
    g_wzm[j] = w6 * a1;
    g_b1[j]  = (b1[j] - m1[j]) * a1 + beta1[j];

    float a2 = g2[j] * rsqrtf(v2[j] + EPSF);
    for (int k = 0; k < 64; k++)
        g_w2[k * 64 + j] = W2[k * 64 + j] * a2;
    g_b2[j] = (b2[j] - m2[j]) * a2 + beta2[j];
}

// ---------------------------------------------------------------------------
// Main kernel: 64 threads per CTA, one pillar at a time (grid-stride).
// lane c = threadIdx.x owns output channel c. W2'[:,c] lives in 64 registers.
// Only points m < npts are computed; relu/bias folded out of the max loop.
// NOTE: coords / npts are int32 (JAX silently downgrades int64 without x64).
// ---------------------------------------------------------------------------
__global__ __launch_bounds__(64) void pfn_main(const float4* __restrict__ pillars,
                                               const int* __restrict__ coords,
                                               const int* __restrict__ npts,
                                               float* __restrict__ out, int P) {
    __shared__ float4 s_pts[32];      // current pillar raw points (x,y,z,r)
    __shared__ float  s_h1[32][64];   // layer-1 activations per point

    const int c    = threadIdx.x;     // channel 0..63
    const int lane = c & 31;

    // Persistent per-lane weights
    float w2r[64];
#pragma unroll
    for (int j = 0; j < 64; j++) w2r[j] = g_w2[j * 64 + c];
    const float wx = g_wx[c], wy = g_wy[c], wz = g_wz[c], wr = g_wr[c];
    const float wxc = g_wxc[c], wyc = g_wyc[c], wzm = g_wzm[c];
    const float b1c = g_b1[c], b2c = g_b2[c];

    for (int p = blockIdx.x; p < P; p += gridDim.x) {
        __syncthreads();  // previous pillar's layer-2 reads of s_h1/s_pts done

        if (threadIdx.x < 32)
            s_pts[threadIdx.x] = pillars[(long long)p * 32 + threadIdx.x];

        int cy = coords[2 * p];
        int cx = coords[2 * p + 1];
        int n = npts[p];
        n = n < 0 ? 0 : (n > 32 ? 32 : n);
        const float xc = ((float)cx + 0.5f) * RESF + XMINF;
        const float yc = ((float)cy + 0.5f) * RESF + YMINF;

        __syncthreads();  // s_pts visible

        // z-mean over valid points (warp-redundant reduce; both warps same result)
        float zv = (lane < n) ? s_pts[lane].z : 0.0f;
#pragma unroll
        for (int o = 16; o > 0; o >>= 1)
            zv += __shfl_xor_sync(0xffffffffu, zv, o);
        const float zm = zv / fmaxf((float)n, 1.0f);

        const float bias = b1c - xc * wxc - yc * wyc - zm * wzm;

        // Layer 1: each thread computes its channel for every valid point
        for (int m = 0; m < n; m++) {
            float4 q = s_pts[m];
            float h = q.x * wx + q.y * wy + q.z * wz + q.w * wr + bias;
            s_h1[m][c] = fmaxf(h, 0.0f);
        }
        __syncthreads();  // s_h1 visible

        // Layer 2 + running max over points (relu/bias applied after the max)
        float mx = NEGF;
        for (int m = 0; m < n; m++) {
            const float4* h4 = (const float4*)s_h1[m];
            float a0 = 0.f, a1 = 0.f, a2 = 0.f, a3 = 0.f;
#pragma unroll
            for (int j4 = 0; j4 < 16; j4++) {
                float4 h = h4[j4];
                int j = j4 * 4;
                a0 = fmaf(h.x, w2r[j + 0], a0);
                a1 = fmaf(h.y, w2r[j + 1], a1);
                a2 = fmaf(h.z, w2r[j + 2], a2);
                a3 = fmaf(h.w, w2r[j + 3], a3);
            }
            mx = fmaxf(mx, (a0 + a1) + (a2 + a3));
        }

        float res = (n > 0) ? fmaxf(mx + b2c, 0.0f) : NEGF;
        out[(long long)p * 64 + c] = res;
    }
}

// ---------------------------------------------------------------------------
// kernel_launch
// Inputs (metadata order):
//  0 pillars f32 (P,32,4)   1 pillar_coords i32 (P,2)   2 num_points i32 (P,)
//  3 W1  4 b1  5 g1  6 beta1  7 m1  8 v1
//  9 W2 10 b2 11 g2 12 beta2 13 m2 14 v2
// Output: f32 (P, 64)
// ---------------------------------------------------------------------------
extern "C" void kernel_launch(void* const* d_in, const int* in_sizes, int n_in,
                              void* d_out, int out_size) {
    const float4* pillars = (const float4*)d_in[0];
    const int*    coords  = (const int*)d_in[1];
    const int*    npts    = (const int*)d_in[2];
    const int P = in_sizes[2];

    pfn_prep<<<1, 64>>>((const float*)d_in[3], (const float*)d_in[4],
                        (const float*)d_in[5], (const float*)d_in[6],
                        (const float*)d_in[7], (const float*)d_in[8],
                        (const float*)d_in[9], (const float*)d_in[10],
                        (const float*)d_in[11], (const float*)d_in[12],
                        (const float*)d_in[13], (const float*)d_in[14]);

    int grid = 4736;               // 32 * 148, amortizes weight-register fill
    if (grid > P) grid = P;
    pfn_main<<<grid, 64>>>(pillars, coords, npts, (float*)d_out, P);
}

// round 4
// speedup vs baseline: 1.0345x; 1.0345x over previous
#include <cuda_runtime.h>

#define RESF  0.16f
#define XMINF -51.2f
#define YMINF -51.2f
#define EPSF  1e-5f
#define NEGF  -1000000000.0f

// Folded layer-1 weights (BN fused, 9-feature input collapsed to 4 + pillar bias)
__device__ float g_wx[64], g_wy[64], g_wz[64], g_wr[64];
__device__ float g_wxc[64], g_wyc[64], g_wzm[64], g_b1[64];
__device__ float g_b2[64];
// Layer-2 weights, BN-folded, packed per channel as (w[2t][c], w[2t+1][c]) u64 pairs:
// g_w2p[c*32 + t]
__device__ unsigned long long g_w2p[64 * 32];

// ---------------------------------------------------------------------------
// Prep kernel (thread j = output channel j)
// ---------------------------------------------------------------------------
__global__ void pfn_prep(const float* __restrict__ W1, const float* __restrict__ b1,
                         const float* __restrict__ g1, const float* __restrict__ beta1,
                         const float* __restrict__ m1, const float* __restrict__ v1,
                         const float* __restrict__ W2, const float* __restrict__ b2,
                         const float* __restrict__ g2, const float* __restrict__ beta2,
                         const float* __restrict__ m2, const float* __restrict__ v2) {
    int j = threadIdx.x;
    if (j >= 64) return;
    float a1 = g1[j] * rsqrtf(v1[j] + EPSF);
    float w4 = W1[4 * 64 + j], w5 = W1[5 * 64 + j], w6 = W1[6 * 64 + j];
    float w7 = W1[7 * 64 + j], w8 = W1[8 * 64 + j];
    g_wx[j]  = (W1[0 * 64 + j] + w4 + w7) * a1;
    g_wy[j]  = (W1[1 * 64 + j] + w5 + w8) * a1;
    g_wz[j]  = (W1[2 * 64 + j] + w6) * a1;
    g_wr[j]  = W1[3 * 64 + j] * a1;
    g_wxc[j] = (w4 + w7) * a1;
    g_wyc[j] = (w5 + w8) * a1;
    g_wzm[j] = w6 * a1;
    g_b1[j]  = (b1[j] - m1[j]) * a1 + beta1[j];

    float a2 = g2[j] * rsqrtf(v2[j] + EPSF);
    for (int t = 0; t < 32; t++) {
        float lo = W2[(2 * t)     * 64 + j] * a2;
        float hi = W2[(2 * t + 1) * 64 + j] * a2;
        unsigned long long pk = ((unsigned long long)__float_as_uint(hi) << 32)
                              |  (unsigned long long)__float_as_uint(lo);
        g_w2p[j * 32 + t] = pk;
    }
    g_b2[j] = (b2[j] - m2[j]) * a2 + beta2[j];
}

// Packed f32x2 helpers (sm_100+ only; ptxas never auto-generates FFMA2)
#define FMA2(acc, a, b) \
    asm("fma.rn.f32x2 %0, %1, %2, %0;" : "+l"(acc) : "l"(a), "l"(b))
#define ADD2(d, a, b) \
    asm("add.rn.f32x2 %0, %1, %2;" : "=l"(d) : "l"(a), "l"(b))
#define UNPK2(lo, hi, v) \
    asm("mov.b64 {%0, %1}, %2;" : "=f"(lo), "=f"(hi) : "l"(v))

// ---------------------------------------------------------------------------
// Main kernel: 1 warp = 1 pillar (warp-private smem slice, no CTA barriers).
// Lane owns output channels (lane, lane+32). Layer-2 inner product runs as
// FFMA2 over consecutive-j pairs; multiplier pairs come straight off LDS.128.
// coords/npts are int32 (JAX downgrades int64 without x64 mode).
// ---------------------------------------------------------------------------
__global__ __launch_bounds__(64, 6) void pfn_main(const float4* __restrict__ pillars,
                                                  const int* __restrict__ coords,
                                                  const int* __restrict__ npts,
                                                  float* __restrict__ out, int P) {
    __shared__ __align__(16) float  s_h1[2][32][64];   // per-warp layer-1 activations
    __shared__ __align__(16) float4 s_pts[2][32];      // per-warp raw points

    const int w    = threadIdx.x >> 5;   // warp within CTA (pillar stream)
    const int lane = threadIdx.x & 31;
    const int cA   = lane;               // first channel
    const int cB   = lane + 32;          // second channel

    // Persistent per-lane weights: 32 packed u64 pairs per channel
    unsigned long long wA[32], wB[32];
#pragma unroll
    for (int t = 0; t < 32; t++) wA[t] = g_w2p[cA * 32 + t];
#pragma unroll
    for (int t = 0; t < 32; t++) wB[t] = g_w2p[cB * 32 + t];

    const float wxA = g_wx[cA], wyA = g_wy[cA], wzA = g_wz[cA], wrA = g_wr[cA];
    const float wxB = g_wx[cB], wyB = g_wy[cB], wzB = g_wz[cB], wrB = g_wr[cB];
    const float xcA = g_wxc[cA], ycA = g_wyc[cA], zmA = g_wzm[cA], b1A = g_b1[cA];
    const float xcB = g_wxc[cB], ycB = g_wyc[cB], zmB = g_wzm[cB], b1B = g_b1[cB];
    const float b2A = g_b2[cA], b2B = g_b2[cB];

    for (int p = blockIdx.x * 2 + w; p < P; p += gridDim.x * 2) {
        __syncwarp();  // previous pillar's s_h1/s_pts reads complete

        // Each lane loads one raw point; stash for broadcast
        float4 q = pillars[(long long)p * 32 + lane];
        s_pts[w][lane] = q;

        int n = npts[p];
        n = n < 0 ? 0 : (n > 32 ? 32 : n);
        const float xc = ((float)coords[2 * p + 1] + 0.5f) * RESF + XMINF;
        const float yc = ((float)coords[2 * p]     + 0.5f) * RESF + YMINF;

        // z-mean over valid points (warp shuffle reduce)
        float zv = (lane < n) ? q.z : 0.0f;
#pragma unroll
        for (int o = 16; o > 0; o >>= 1)
            zv += __shfl_xor_sync(0xffffffffu, zv, o);
        const float zm = zv / fmaxf((float)n, 1.0f);

        const float biasA = b1A - xc * xcA - yc * ycA - zm * zmA;
        const float biasB = b1B - xc * xcB - yc * ycB - zm * zmB;

        __syncwarp();  // s_pts visible

        // Layer 1: both channels for every valid point
        for (int m = 0; m < n; m++) {
            float4 qm = s_pts[w][m];
            float hA = fmaf(qm.x, wxA, fmaf(qm.y, wyA,
                       fmaf(qm.z, wzA, fmaf(qm.w, wrA, biasA))));
            float hB = fmaf(qm.x, wxB, fmaf(qm.y, wyB,
                       fmaf(qm.z, wzB, fmaf(qm.w, wrB, biasB))));
            s_h1[w][m][cA] = fmaxf(hA, 0.0f);
            s_h1[w][m][cB] = fmaxf(hB, 0.0f);
        }
        __syncwarp();  // s_h1 visible

        // Layer 2 + running max (16 LDS.128 + 64 FFMA2 per point, warp-wide)
        float mxA = NEGF, mxB = NEGF;
        for (int m = 0; m < n; m++) {
            const ulonglong2* hp = (const ulonglong2*)s_h1[w][m];
            unsigned long long a0A = 0ull, a1A = 0ull, a0B = 0ull, a1B = 0ull;
#pragma unroll
            for (int t = 0; t < 16; t++) {
                ulonglong2 hv = hp[t];      // (h[4t],h[4t+1]) | (h[4t+2],h[4t+3])
                FMA2(a0A, hv.x, wA[2 * t]);
                FMA2(a1A, hv.y, wA[2 * t + 1]);
                FMA2(a0B, hv.x, wB[2 * t]);
                FMA2(a1B, hv.y, wB[2 * t + 1]);
            }
            unsigned long long sA, sB;
            ADD2(sA, a0A, a1A);
            ADD2(sB, a0B, a1B);
            float loA, hiA, loB, hiB;
            UNPK2(loA, hiA, sA);
            UNPK2(loB, hiB, sB);
            mxA = fmaxf(mxA, loA + hiA);
            mxB = fmaxf(mxB, loB + hiB);
        }

        float rA = (n > 0) ? fmaxf(mxA + b2A, 0.0f) : NEGF;
        float rB = (n > 0) ? fmaxf(mxB + b2B, 0.0f) : NEGF;
        out[(long long)p * 64 + cA] = rA;
        out[(long long)p * 64 + cB] = rB;
    }
}

// ---------------------------------------------------------------------------
// kernel_launch
// Inputs: 0 pillars f32 (P,32,4)  1 coords i32 (P,2)  2 npts i32 (P,)
//         3 W1 4 b1 5 g1 6 beta1 7 m1 8 v1  9 W2 10 b2 11 g2 12 beta2 13 m2 14 v2
// Output: f32 (P, 64)
// ---------------------------------------------------------------------------
extern "C" void kernel_launch(void* const* d_in, const int* in_sizes, int n_in,
                              void* d_out, int out_size) {
    const float4* pillars = (const float4*)d_in[0];
    const int*    coords  = (const int*)d_in[1];
    const int*    npts    = (const int*)d_in[2];
    const int P = in_sizes[2];

    pfn_prep<<<1, 64>>>((const float*)d_in[3], (const float*)d_in[4],
                        (const float*)d_in[5], (const float*)d_in[6],
                        (const float*)d_in[7], (const float*)d_in[8],
                        (const float*)d_in[9], (const float*)d_in[10],
                        (const float*)d_in[11], (const float*)d_in[12],
                        (const float*)d_in[13], (const float*)d_in[14]);

    int grid = 2368;                       // 2 pillar streams per CTA -> 4736 streams
    if (grid * 2 > P) grid = (P + 1) / 2;
    pfn_main<<<grid, 64>>>(pillars, coords, npts, (float*)d_out, P);
}